// round 1
// baseline (speedup 1.0000x reference)
#include <cuda_runtime.h>

// ---------------------------------------------------------------------------
// AutoEncoder_BNN: batch=8192, n_x=4096, n_rbf=1024, n_bus=2048
//   h1 = relu(x @ W_h^T + b_h)            [8192,1024]  K=4096
//   h2 = relu(h1 @ W_h2^T + b_h2)         [8192,1024]  K=1024
//   uw = h2 @ W_y^T + b_y                 [8192,4096]  K=1024   -> out[0]
//   u = uw[:, :2048], w = uw[:, 2048:]
//   Gu=u@G^T Gw=w@G^T Bu=u@Bm^T Bw=w@Bm^T [8192,2048]  K=2048
//   pp = u*Gu + w*Gw + w*Bu - u*Bw + bias_p
//   qp = w*Gu - u*Gw - u*Bu - w*Bw + bias_q
//   p  = pp @ W_p^T + b_p                 [8192,2048]  K=2048   -> out[1]
//   q  = qp @ W_q^T + b_q                 [8192,2048]  K=2048   -> out[2]
// All GEMMs are NT (both operands K-contiguous). All dims divide tile sizes.
// ---------------------------------------------------------------------------

#define BM 128
#define BN 128
#define BK 16
#define NTHREADS 256

// Scratch (static device globals; no runtime allocation)
__device__ float g_h1[8192L * 1024];
__device__ float g_h2[8192L * 1024];
__device__ float g_Gu[8192L * 2048];
__device__ float g_Gw[8192L * 2048];
__device__ float g_Bu[8192L * 2048];
__device__ float g_Bw[8192L * 2048];
__device__ float g_pp[8192L * 2048];
__device__ float g_qp[8192L * 2048];

// C[M,N] = act(A[M,K] @ B[N,K]^T + bias), row-major, strides lda/ldb/ldc.
// Requires: M%128==0, N%128==0, K%16==0, 16B-aligned pointers/strides.
template <bool RELU, bool HAS_BIAS>
__global__ __launch_bounds__(NTHREADS)
void gemm_nt(const float* __restrict__ A, int lda,
             const float* __restrict__ B, int ldb,
             const float* __restrict__ bias,
             float* __restrict__ C, int ldc, int K)
{
    __shared__ float As[BK][BM];
    __shared__ float Bs[BK][BN];

    const int tid  = threadIdx.x;
    const int row0 = blockIdx.y * BM;
    const int col0 = blockIdx.x * BN;

    const float* Ap = A + (size_t)row0 * lda;
    const float* Bp = B + (size_t)col0 * ldb;

    const int tx = tid & 15;   // 0..15 -> N microtile
    const int ty = tid >> 4;   // 0..15 -> M microtile

    // Global->shared loader mapping: float4 f = tid (+256): row = f>>2, kc = (f&3)*4
    const int lrow = tid >> 2;        // 0..63
    const int lkc  = (tid & 3) << 2;  // 0,4,8,12

    float acc[8][8];
#pragma unroll
    for (int i = 0; i < 8; ++i)
#pragma unroll
        for (int j = 0; j < 8; ++j) acc[i][j] = 0.0f;

    for (int k0 = 0; k0 < K; k0 += BK) {
        const float4 a0 = *reinterpret_cast<const float4*>(Ap + (size_t)lrow        * lda + k0 + lkc);
        const float4 a1 = *reinterpret_cast<const float4*>(Ap + (size_t)(lrow + 64) * lda + k0 + lkc);
        const float4 b0 = *reinterpret_cast<const float4*>(Bp + (size_t)lrow        * ldb + k0 + lkc);
        const float4 b1 = *reinterpret_cast<const float4*>(Bp + (size_t)(lrow + 64) * ldb + k0 + lkc);

        __syncthreads();  // previous tile's compute must finish before overwrite

        As[lkc + 0][lrow]      = a0.x; As[lkc + 1][lrow]      = a0.y;
        As[lkc + 2][lrow]      = a0.z; As[lkc + 3][lrow]      = a0.w;
        As[lkc + 0][lrow + 64] = a1.x; As[lkc + 1][lrow + 64] = a1.y;
        As[lkc + 2][lrow + 64] = a1.z; As[lkc + 3][lrow + 64] = a1.w;
        Bs[lkc + 0][lrow]      = b0.x; Bs[lkc + 1][lrow]      = b0.y;
        Bs[lkc + 2][lrow]      = b0.z; Bs[lkc + 3][lrow]      = b0.w;
        Bs[lkc + 0][lrow + 64] = b1.x; Bs[lkc + 1][lrow + 64] = b1.y;
        Bs[lkc + 2][lrow + 64] = b1.z; Bs[lkc + 3][lrow + 64] = b1.w;

        __syncthreads();

#pragma unroll
        for (int k = 0; k < BK; ++k) {
            float a[8], b[8];
            float4 t;
            t = *reinterpret_cast<const float4*>(&As[k][ty * 4]);
            a[0] = t.x; a[1] = t.y; a[2] = t.z; a[3] = t.w;
            t = *reinterpret_cast<const float4*>(&As[k][64 + ty * 4]);
            a[4] = t.x; a[5] = t.y; a[6] = t.z; a[7] = t.w;
            t = *reinterpret_cast<const float4*>(&Bs[k][tx * 4]);
            b[0] = t.x; b[1] = t.y; b[2] = t.z; b[3] = t.w;
            t = *reinterpret_cast<const float4*>(&Bs[k][64 + tx * 4]);
            b[4] = t.x; b[5] = t.y; b[6] = t.z; b[7] = t.w;
#pragma unroll
            for (int i = 0; i < 8; ++i)
#pragma unroll
                for (int j = 0; j < 8; ++j)
                    acc[i][j] += a[i] * b[j];
        }
    }

    float bb[8];
    if (HAS_BIAS) {
#pragma unroll
        for (int j = 0; j < 4; ++j) {
            bb[j]     = bias[col0 + tx * 4 + j];
            bb[4 + j] = bias[col0 + 64 + tx * 4 + j];
        }
    } else {
#pragma unroll
        for (int j = 0; j < 8; ++j) bb[j] = 0.0f;
    }

#pragma unroll
    for (int i = 0; i < 8; ++i) {
        const int r = row0 + ((i < 4) ? (ty * 4 + i) : (64 + ty * 4 + (i - 4)));
        float* Cr = C + (size_t)r * ldc;
        float4 v0, v1;
        v0.x = acc[i][0] + bb[0]; v0.y = acc[i][1] + bb[1];
        v0.z = acc[i][2] + bb[2]; v0.w = acc[i][3] + bb[3];
        v1.x = acc[i][4] + bb[4]; v1.y = acc[i][5] + bb[5];
        v1.z = acc[i][6] + bb[6]; v1.w = acc[i][7] + bb[7];
        if (RELU) {
            v0.x = fmaxf(v0.x, 0.0f); v0.y = fmaxf(v0.y, 0.0f);
            v0.z = fmaxf(v0.z, 0.0f); v0.w = fmaxf(v0.w, 0.0f);
            v1.x = fmaxf(v1.x, 0.0f); v1.y = fmaxf(v1.y, 0.0f);
            v1.z = fmaxf(v1.z, 0.0f); v1.w = fmaxf(v1.w, 0.0f);
        }
        *reinterpret_cast<float4*>(Cr + col0 + tx * 4)      = v0;
        *reinterpret_cast<float4*>(Cr + col0 + 64 + tx * 4) = v1;
    }
}

// pp/qp = polar power-flow combine from uw (u|w) and the four mix GEMMs.
__global__ __launch_bounds__(256)
void combine_kernel(const float* __restrict__ uw,
                    const float* __restrict__ Gu, const float* __restrict__ Gw,
                    const float* __restrict__ Bu, const float* __restrict__ Bw,
                    const float* __restrict__ bias_p, const float* __restrict__ bias_q,
                    float* __restrict__ pp, float* __restrict__ qp)
{
    const int idx = blockIdx.x * 256 + threadIdx.x;   // [0, 8192*2048)
    const int row = idx >> 11;
    const int col = idx & 2047;
    const float u = uw[(size_t)row * 4096 + col];
    const float w = uw[(size_t)row * 4096 + 2048 + col];
    const float gu = Gu[idx], gw = Gw[idx], bu = Bu[idx], bw = Bw[idx];
    pp[idx] = u * gu + w * gw + w * bu - u * bw + bias_p[col];
    qp[idx] = w * gu - u * gw - u * bu - w * bw + bias_q[col];
}

extern "C" void kernel_launch(void* const* d_in, const int* in_sizes, int n_in,
                              void* d_out, int out_size)
{
    const float* x      = (const float*)d_in[0];
    const float* W_h    = (const float*)d_in[1];
    const float* b_h    = (const float*)d_in[2];
    const float* W_h2   = (const float*)d_in[3];
    const float* b_h2   = (const float*)d_in[4];
    const float* W_y    = (const float*)d_in[5];
    const float* b_y    = (const float*)d_in[6];
    const float* G      = (const float*)d_in[7];
    const float* Bm     = (const float*)d_in[8];
    const float* bias_p = (const float*)d_in[9];
    const float* bias_q = (const float*)d_in[10];
    const float* W_p    = (const float*)d_in[11];
    const float* b_p    = (const float*)d_in[12];
    const float* W_q    = (const float*)d_in[13];
    const float* b_q    = (const float*)d_in[14];

    float* out = (float*)d_out;
    float* uw  = out;                                   // [8192,4096]
    float* p   = out + (size_t)8192 * 4096;             // [8192,2048]
    float* q   = p   + (size_t)8192 * 2048;             // [8192,2048]

    float *h1, *h2, *Gu, *Gw, *Bu, *Bw, *pp, *qp;
    cudaGetSymbolAddress((void**)&h1, g_h1);
    cudaGetSymbolAddress((void**)&h2, g_h2);
    cudaGetSymbolAddress((void**)&Gu, g_Gu);
    cudaGetSymbolAddress((void**)&Gw, g_Gw);
    cudaGetSymbolAddress((void**)&Bu, g_Bu);
    cudaGetSymbolAddress((void**)&Bw, g_Bw);
    cudaGetSymbolAddress((void**)&pp, g_pp);
    cudaGetSymbolAddress((void**)&qp, g_qp);

    const int M = 8192;
    const dim3 blk(NTHREADS);
    const dim3 g1024(1024 / BN, M / BM);
    const dim3 g2048(2048 / BN, M / BM);
    const dim3 g4096(4096 / BN, M / BM);

    // MLP trunk
    gemm_nt<true,  true><<<g1024, blk>>>(x,  4096, W_h,  4096, b_h,  h1, 1024, 4096);
    gemm_nt<true,  true><<<g1024, blk>>>(h1, 1024, W_h2, 1024, b_h2, h2, 1024, 1024);
    gemm_nt<false, true><<<g4096, blk>>>(h2, 1024, W_y,  1024, b_y,  uw, 4096, 1024);

    // Mixing GEMMs: u = uw[:, :2048] (lda=4096), w = uw[:, 2048:]
    const float* u_ptr = uw;
    const float* w_ptr = uw + 2048;
    gemm_nt<false, false><<<g2048, blk>>>(u_ptr, 4096, G,  2048, nullptr, Gu, 2048, 2048);
    gemm_nt<false, false><<<g2048, blk>>>(w_ptr, 4096, G,  2048, nullptr, Gw, 2048, 2048);
    gemm_nt<false, false><<<g2048, blk>>>(u_ptr, 4096, Bm, 2048, nullptr, Bu, 2048, 2048);
    gemm_nt<false, false><<<g2048, blk>>>(w_ptr, 4096, Bm, 2048, nullptr, Bw, 2048, 2048);

    // Elementwise polar combine
    combine_kernel<<<(8192L * 2048) / 256, 256>>>(uw, Gu, Gw, Bu, Bw, bias_p, bias_q, pp, qp);

    // Output GEMMs
    gemm_nt<false, true><<<g2048, blk>>>(pp, 2048, W_p, 2048, b_p, p, 2048, 2048);
    gemm_nt<false, true><<<g2048, blk>>>(qp, 2048, W_q, 2048, b_q, q, 2048, 2048);
}

// round 4
// speedup vs baseline: 2.9493x; 2.9493x over previous
#include <cuda_runtime.h>
#include <cuda_bf16.h>
#include <cstdint>

// ============================================================================
// AutoEncoder_BNN via mma.sync bf16 (portable to plain sm_103 ptxas target).
// fp32 GEMMs emulated as bf16 NT GEMM with K'=3K:
//   a = a_hi + a_lo :  A_cat = [A_hi | A_lo | A_hi],  B_cat = [B_hi | B_hi | B_lo]
//   => hi*hi + lo*hi + hi*lo  (dropped lo*lo ~2^-16 rel), fp32 accumulate.
// Engine: 128x128x64 tile, 8 warps (2x4), warp tile 64x32, m16n8k16 HMMA,
// 3-stage cp.async pipeline, SW128 swizzle, conflict-free ldmatrix.x4.
// R4 fix: weights (B side) are packed [hi|hi|lo]; activations (A side)
// [hi|lo|hi]. Round 3 packed BOTH as [hi|lo|hi] => hi*hi+lo*lo+hi*hi ~ 2x per
// GEMM => 8x on uw (rel_err 6.9 observed).
// ============================================================================

// ---------------- device scratch (static; no runtime allocation) ------------
__device__ __nv_bfloat16 g_xcat [8192L  * 12288];  // x split      [8192,3*4096]
__device__ __nv_bfloat16 g_whcat[1024L  * 12288];  // W_h split
__device__ __nv_bfloat16 g_h1cat[8192L  * 3072];   // h1 split     [8192,3*1024]
__device__ __nv_bfloat16 g_wh2cat[1024L * 3072];
__device__ __nv_bfloat16 g_h2cat[8192L  * 3072];
__device__ __nv_bfloat16 g_wycat[4096L  * 3072];   // W_y split
__device__ __nv_bfloat16 g_uwcat[16384L * 6144];   // [u;w] split  [16384,3*2048]
__device__ __nv_bfloat16 g_gbmcat[4096L * 6144];   // [G;Bm] split
__device__ float         g_mix  [16384L * 4096];   // [Gu|Bu ; Gw|Bw]
__device__ __nv_bfloat16 g_ppcat[8192L  * 6144];
__device__ __nv_bfloat16 g_qpcat[8192L  * 6144];
__device__ __nv_bfloat16 g_wpcat[2048L  * 6144];
__device__ __nv_bfloat16 g_wqcat[2048L  * 6144];

// ---------------- PTX helpers ------------------------------------------------
__device__ __forceinline__ uint32_t smem_u32(const void* p) {
    uint32_t a;
    asm("{ .reg .u64 t; cvta.to.shared.u64 t, %1; cvt.u32.u64 %0, t; }" : "=r"(a) : "l"(p));
    return a;
}
__device__ __forceinline__ void cp_async16(uint32_t dst, const void* src) {
    asm volatile("cp.async.cg.shared.global [%0], [%1], 16;" :: "r"(dst), "l"(src) : "memory");
}
__device__ __forceinline__ void cp_commit() {
    asm volatile("cp.async.commit_group;" ::: "memory");
}
__device__ __forceinline__ void cp_wait1() {
    asm volatile("cp.async.wait_group 1;" ::: "memory");
}
__device__ __forceinline__ void ldsm4(uint32_t* r, uint32_t addr) {
    asm volatile("ldmatrix.sync.aligned.m8n8.x4.shared.b16 {%0,%1,%2,%3}, [%4];"
                 : "=r"(r[0]), "=r"(r[1]), "=r"(r[2]), "=r"(r[3]) : "r"(addr));
}
__device__ __forceinline__ void mma16816(float* c, const uint32_t* a, uint32_t b0, uint32_t b1) {
    asm volatile(
        "mma.sync.aligned.m16n8k16.row.col.f32.bf16.bf16.f32 "
        "{%0,%1,%2,%3}, {%4,%5,%6,%7}, {%8,%9}, {%0,%1,%2,%3};"
        : "+f"(c[0]), "+f"(c[1]), "+f"(c[2]), "+f"(c[3])
        : "r"(a[0]), "r"(a[1]), "r"(a[2]), "r"(a[3]), "r"(b0), "r"(b1));
}
__device__ __forceinline__ void split2(float a, float b, __nv_bfloat162& h, __nv_bfloat162& l) {
    __nv_bfloat16 ha = __float2bfloat16(a);
    __nv_bfloat16 hb = __float2bfloat16(b);
    h.x = ha; h.y = hb;
    l.x = __float2bfloat16(a - __bfloat162float(ha));
    l.y = __float2bfloat16(b - __bfloat162float(hb));
}

// ---------------- mma.sync GEMM ----------------------------------------------
// C[M,N] = act(A[M,K'] @ B[N,K']^T + bias); A,B bf16 K-major, fp32 accum.
// MODE 0: write fp32 C.
// MODE 1: write bf16 split (hi|lo|hi) to S with row stride 3*Nfull.
// MODE 2: write fp32 C (uw) AND split into stacked u/w buffer S [16384,6144].
constexpr int SMEM_BYTES = 3 * 32768;   // 3 stages x (A 16KB + B 16KB)

template <int MODE, bool RELU, bool BIAS>
__global__ __launch_bounds__(256, 2)
void gemm_mma(const __nv_bfloat16* __restrict__ A, int lda,
              const __nv_bfloat16* __restrict__ B, int ldb,
              const float* __restrict__ bias,
              float* __restrict__ C, int ldc,
              __nv_bfloat16* __restrict__ S, int Nfull, int K)
{
    extern __shared__ __align__(1024) char smem[];
    const uint32_t sb = smem_u32(smem);
    const int tid = threadIdx.x, lane = tid & 31, wid = tid >> 5;
    const int wm = wid & 1, wn = wid >> 1;            // warp grid 2(m) x 4(n)
    const int m0 = blockIdx.y * 128, n0 = blockIdx.x * 128;

    // ---- global->shared loader mapping (16B chunks, SW128 swizzle) ----
    const int lrow = tid >> 3;        // 0..31 (4 waves of 32 rows)
    const int lc16 = tid & 7;         // 16B chunk within 128B row
    uint32_t ld_off[4];
#pragma unroll
    for (int w2 = 0; w2 < 4; ++w2) {
        const int r = lrow + w2 * 32;
        ld_off[w2] = r * 128 + ((lc16 * 16) ^ ((r & 7) << 4));
    }
    const __nv_bfloat16* Ag = A + (size_t)(m0 + lrow) * lda + lc16 * 8;
    const __nv_bfloat16* Bg = B + (size_t)(n0 + lrow) * ldb + lc16 * 8;

    // ---- ldmatrix address precompute ----
    uint32_t aTerm[4], aXor[4];
#pragma unroll
    for (int mt = 0; mt < 4; ++mt) {
        const int r = wm * 64 + mt * 16 + ((lane >> 3) & 1) * 8 + (lane & 7);
        aTerm[mt] = r * 128; aXor[mt] = (r & 7) << 4;
    }
    const uint32_t aCol = (lane >> 4) * 16;
    uint32_t bTerm[2], bXor[2];
#pragma unroll
    for (int nt = 0; nt < 2; ++nt) {
        const int r = wn * 32 + nt * 16 + (lane >> 4) * 8 + (lane & 7);
        bTerm[nt] = r * 128; bXor[nt] = (r & 7) << 4;
    }
    const uint32_t bCol = ((lane >> 3) & 1) * 16;

    float acc[4][4][4];
#pragma unroll
    for (int mt = 0; mt < 4; ++mt)
#pragma unroll
        for (int n8 = 0; n8 < 4; ++n8)
#pragma unroll
            for (int j = 0; j < 4; ++j) acc[mt][n8][j] = 0.0f;

    const int nst = K / 64;

    auto issue = [&](int s, int kt) {
        const uint32_t sa = sb + (uint32_t)s * 32768u;
#pragma unroll
        for (int w2 = 0; w2 < 4; ++w2)
            cp_async16(sa + ld_off[w2], Ag + (size_t)w2 * 32 * lda + kt);
#pragma unroll
        for (int w2 = 0; w2 < 4; ++w2)
            cp_async16(sa + 16384u + ld_off[w2], Bg + (size_t)w2 * 32 * ldb + kt);
        cp_commit();
    };

    issue(0, 0);
    issue(1, 64);

    for (int i = 0; i < nst; ++i) {
        cp_wait1();
        __syncthreads();
        if (i + 2 < nst) issue((i + 2) % 3, (i + 2) * 64);
        else             cp_commit();            // keep group counting uniform

        const uint32_t sa = sb + (uint32_t)(i % 3) * 32768u;
        const uint32_t sB = sa + 16384u;
#pragma unroll
        for (int kk = 0; kk < 4; ++kk) {
            uint32_t a[4][4], b[2][4];
#pragma unroll
            for (int mt = 0; mt < 4; ++mt)
                ldsm4(a[mt], sa + aTerm[mt] + ((kk * 32 + aCol) ^ aXor[mt]));
#pragma unroll
            for (int nt = 0; nt < 2; ++nt)
                ldsm4(b[nt], sB + bTerm[nt] + ((kk * 32 + bCol) ^ bXor[nt]));
#pragma unroll
            for (int mt = 0; mt < 4; ++mt)
#pragma unroll
                for (int n8 = 0; n8 < 4; ++n8)
                    mma16816(acc[mt][n8], a[mt],
                             b[n8 >> 1][(n8 & 1) * 2], b[n8 >> 1][(n8 & 1) * 2 + 1]);
        }
        __syncthreads();
    }

    // ---- epilogue ----
    float bb[4][2];
#pragma unroll
    for (int n8 = 0; n8 < 4; ++n8) {
        if (BIAS) {
            const int col = n0 + wn * 32 + n8 * 8 + (lane & 3) * 2;
            bb[n8][0] = __ldg(&bias[col]);
            bb[n8][1] = __ldg(&bias[col + 1]);
        } else { bb[n8][0] = 0.0f; bb[n8][1] = 0.0f; }
    }

#pragma unroll
    for (int mt = 0; mt < 4; ++mt) {
#pragma unroll
        for (int half = 0; half < 2; ++half) {
            const int r = m0 + wm * 64 + mt * 16 + (lane >> 2) + half * 8;
#pragma unroll
            for (int n8 = 0; n8 < 4; ++n8) {
                const int col = n0 + wn * 32 + n8 * 8 + (lane & 3) * 2;
                float v0 = acc[mt][n8][half * 2 + 0] + bb[n8][0];
                float v1 = acc[mt][n8][half * 2 + 1] + bb[n8][1];
                if (RELU) { v0 = fmaxf(v0, 0.0f); v1 = fmaxf(v1, 0.0f); }
                if (MODE == 0 || MODE == 2)
                    *reinterpret_cast<float2*>(C + (size_t)r * ldc + col) = make_float2(v0, v1);
                if (MODE == 1) {
                    __nv_bfloat162 h, l; split2(v0, v1, h, l);
                    __nv_bfloat16* Sr = S + (size_t)r * (3 * Nfull) + col;
                    *reinterpret_cast<__nv_bfloat162*>(Sr)             = h;
                    *reinterpret_cast<__nv_bfloat162*>(Sr + Nfull)     = l;
                    *reinterpret_cast<__nv_bfloat162*>(Sr + 2 * Nfull) = h;
                }
                if (MODE == 2) {   // stacked: u rows [0,8192) | w rows [8192,16384)
                    const bool inU = (col < 2048);
                    const int rr = inU ? r : r + 8192;
                    const int cc = inU ? col : col - 2048;
                    __nv_bfloat162 h, l; split2(v0, v1, h, l);
                    __nv_bfloat16* Sr = S + (size_t)rr * 6144 + cc;
                    *reinterpret_cast<__nv_bfloat162*>(Sr)        = h;
                    *reinterpret_cast<__nv_bfloat162*>(Sr + 2048) = l;
                    *reinterpret_cast<__nv_bfloat162*>(Sr + 4096) = h;
                }
            }
        }
    }
}

// ------- pack: fp32 [R,C] -> bf16 split [R, 3C] -----------------------------
// B_SIDE=false (A operand): [hi | lo | hi].  B_SIDE=true (weights): [hi | hi | lo].
template <bool B_SIDE>
__global__ __launch_bounds__(256)
void pack2(const float* __restrict__ src, __nv_bfloat16* __restrict__ dst,
           int logC, long total)
{
    const long i = ((long)blockIdx.x * 256 + threadIdx.x) * 2;
    if (i >= total) return;
    const int  C = 1 << logC;
    const long r = i >> logC;
    const int  c = (int)(i & (C - 1));
    const float2 v = *reinterpret_cast<const float2*>(src + i);
    __nv_bfloat162 h, l; split2(v.x, v.y, h, l);
    __nv_bfloat16* d = dst + r * (3L * C) + c;
    if (B_SIDE) {
        *reinterpret_cast<__nv_bfloat162*>(d)         = h;
        *reinterpret_cast<__nv_bfloat162*>(d + C)     = h;
        *reinterpret_cast<__nv_bfloat162*>(d + 2 * C) = l;
    } else {
        *reinterpret_cast<__nv_bfloat162*>(d)         = h;
        *reinterpret_cast<__nv_bfloat162*>(d + C)     = l;
        *reinterpret_cast<__nv_bfloat162*>(d + 2 * C) = h;
    }
}

// ---------------- polar combine -> split pp/qp ------------------------------
__global__ __launch_bounds__(256)
void combine(const float* __restrict__ uw, const float* __restrict__ mix,
             const float* __restrict__ bias_p, const float* __restrict__ bias_q,
             __nv_bfloat16* __restrict__ ppcat, __nv_bfloat16* __restrict__ qpcat)
{
    const long i = ((long)blockIdx.x * 256 + threadIdx.x) * 2;   // [0, 8192*2048)
    const long r = i >> 11;
    const int  c = (int)(i & 2047);
    const float2 u2 = *reinterpret_cast<const float2*>(uw + r * 4096 + c);
    const float2 w2 = *reinterpret_cast<const float2*>(uw + r * 4096 + 2048 + c);
    const float2 gu = *reinterpret_cast<const float2*>(mix + r * 4096 + c);
    const float2 bu = *reinterpret_cast<const float2*>(mix + r * 4096 + 2048 + c);
    const float2 gw = *reinterpret_cast<const float2*>(mix + (r + 8192) * 4096 + c);
    const float2 bw = *reinterpret_cast<const float2*>(mix + (r + 8192) * 4096 + 2048 + c);
    const float2 bp = *reinterpret_cast<const float2*>(bias_p + c);
    const float2 bq = *reinterpret_cast<const float2*>(bias_q + c);
    const float p0 = u2.x * gu.x + w2.x * gw.x + w2.x * bu.x - u2.x * bw.x + bp.x;
    const float p1 = u2.y * gu.y + w2.y * gw.y + w2.y * bu.y - u2.y * bw.y + bp.y;
    const float q0 = w2.x * gu.x - u2.x * gw.x - u2.x * bu.x - w2.x * bw.x + bq.x;
    const float q1 = w2.y * gu.y - u2.y * gw.y - u2.y * bu.y - w2.y * bw.y + bq.y;
    __nv_bfloat162 h, l;
    __nv_bfloat16* d = ppcat + r * 6144 + c;
    split2(p0, p1, h, l);
    *reinterpret_cast<__nv_bfloat162*>(d)        = h;
    *reinterpret_cast<__nv_bfloat162*>(d + 2048) = l;
    *reinterpret_cast<__nv_bfloat162*>(d + 4096) = h;
    d = qpcat + r * 6144 + c;
    split2(q0, q1, h, l);
    *reinterpret_cast<__nv_bfloat162*>(d)        = h;
    *reinterpret_cast<__nv_bfloat162*>(d + 2048) = l;
    *reinterpret_cast<__nv_bfloat162*>(d + 4096) = h;
}

// ---------------- host side --------------------------------------------------
extern "C" void kernel_launch(void* const* d_in, const int* in_sizes, int n_in,
                              void* d_out, int out_size)
{
    const float* x      = (const float*)d_in[0];
    const float* W_h    = (const float*)d_in[1];
    const float* b_h    = (const float*)d_in[2];
    const float* W_h2   = (const float*)d_in[3];
    const float* b_h2   = (const float*)d_in[4];
    const float* W_y    = (const float*)d_in[5];
    const float* b_y    = (const float*)d_in[6];
    const float* G      = (const float*)d_in[7];
    const float* Bm     = (const float*)d_in[8];
    const float* bias_p = (const float*)d_in[9];
    const float* bias_q = (const float*)d_in[10];
    const float* W_p    = (const float*)d_in[11];
    const float* b_p    = (const float*)d_in[12];
    const float* W_q    = (const float*)d_in[13];
    const float* b_q    = (const float*)d_in[14];

    float* out = (float*)d_out;
    float* uw  = out;                                 // [8192,4096]
    float* p   = out + (size_t)8192 * 4096;           // [8192,2048]
    float* q   = p   + (size_t)8192 * 2048;           // [8192,2048]

    __nv_bfloat16 *xcat, *whcat, *h1cat, *wh2cat, *h2cat, *wycat, *uwcat,
                  *gbmcat, *ppcat, *qpcat, *wpcat, *wqcat;
    float* mix;
    cudaGetSymbolAddress((void**)&xcat,  g_xcat);
    cudaGetSymbolAddress((void**)&whcat, g_whcat);
    cudaGetSymbolAddress((void**)&h1cat, g_h1cat);
    cudaGetSymbolAddress((void**)&wh2cat,g_wh2cat);
    cudaGetSymbolAddress((void**)&h2cat, g_h2cat);
    cudaGetSymbolAddress((void**)&wycat, g_wycat);
    cudaGetSymbolAddress((void**)&uwcat, g_uwcat);
    cudaGetSymbolAddress((void**)&gbmcat,g_gbmcat);
    cudaGetSymbolAddress((void**)&mix,   g_mix);
    cudaGetSymbolAddress((void**)&ppcat, g_ppcat);
    cudaGetSymbolAddress((void**)&qpcat, g_qpcat);
    cudaGetSymbolAddress((void**)&wpcat, g_wpcat);
    cudaGetSymbolAddress((void**)&wqcat, g_wqcat);

    cudaFuncSetAttribute(gemm_mma<1, true,  true >, cudaFuncAttributeMaxDynamicSharedMemorySize, SMEM_BYTES);
    cudaFuncSetAttribute(gemm_mma<2, false, true >, cudaFuncAttributeMaxDynamicSharedMemorySize, SMEM_BYTES);
    cudaFuncSetAttribute(gemm_mma<0, false, false>, cudaFuncAttributeMaxDynamicSharedMemorySize, SMEM_BYTES);
    cudaFuncSetAttribute(gemm_mma<0, false, true >, cudaFuncAttributeMaxDynamicSharedMemorySize, SMEM_BYTES);

    // ---- packs: x is A-side [hi|lo|hi]; all weights are B-side [hi|hi|lo] ----
    pack2<false><<<(8192L * 4096 / 2 + 255) / 256, 256>>>(x,    xcat,   12, 8192L * 4096);
    pack2<true ><<<(1024L * 4096 / 2 + 255) / 256, 256>>>(W_h,  whcat,  12, 1024L * 4096);
    pack2<true ><<<(1024L * 1024 / 2 + 255) / 256, 256>>>(W_h2, wh2cat, 10, 1024L * 1024);
    pack2<true ><<<(4096L * 1024 / 2 + 255) / 256, 256>>>(W_y,  wycat,  10, 4096L * 1024);
    pack2<true ><<<(2048L * 2048 / 2 + 255) / 256, 256>>>(G,    gbmcat,                11, 2048L * 2048);
    pack2<true ><<<(2048L * 2048 / 2 + 255) / 256, 256>>>(Bm,   gbmcat + 2048L * 6144, 11, 2048L * 2048);
    pack2<true ><<<(2048L * 2048 / 2 + 255) / 256, 256>>>(W_p,  wpcat,  11, 2048L * 2048);
    pack2<true ><<<(2048L * 2048 / 2 + 255) / 256, 256>>>(W_q,  wqcat,  11, 2048L * 2048);

    const dim3 blk(256);
    // G1: h1 = relu(x @ W_h^T + b_h)          -> split h1cat
    gemm_mma<1, true,  true ><<<dim3(1024 / 128, 8192 / 128), blk, SMEM_BYTES>>>(
        xcat, 12288, whcat, 12288, b_h, nullptr, 0, h1cat, 1024, 12288);
    // G2: h2 = relu(h1 @ W_h2^T + b_h2)       -> split h2cat
    gemm_mma<1, true,  true ><<<dim3(1024 / 128, 8192 / 128), blk, SMEM_BYTES>>>(
        h1cat, 3072, wh2cat, 3072, b_h2, nullptr, 0, h2cat, 1024, 3072);
    // G3: uw = h2 @ W_y^T + b_y               -> f32 uw (d_out) + stacked split uwcat
    gemm_mma<2, false, true ><<<dim3(4096 / 128, 8192 / 128), blk, SMEM_BYTES>>>(
        h2cat, 3072, wycat, 3072, b_y, uw, 4096, uwcat, 4096, 3072);
    // G4: [Gu|Bu ; Gw|Bw] = [u;w] @ [G;Bm]^T  -> f32 mix
    gemm_mma<0, false, false><<<dim3(4096 / 128, 16384 / 128), blk, SMEM_BYTES>>>(
        uwcat, 6144, gbmcat, 6144, nullptr, mix, 4096, nullptr, 0, 6144);
    // combine -> split pp/qp
    combine<<<(8192L * 2048 / 2) / 256, 256>>>(uw, mix, bias_p, bias_q, ppcat, qpcat);
    // G5/G6: final projections
    gemm_mma<0, false, true ><<<dim3(2048 / 128, 8192 / 128), blk, SMEM_BYTES>>>(
        ppcat, 6144, wpcat, 6144, b_p, p, 2048, nullptr, 0, 6144);
    gemm_mma<0, false, true ><<<dim3(2048 / 128, 8192 / 128), blk, SMEM_BYTES>>>(
        qpcat, 6144, wqcat, 6144, b_q, q, 2048, nullptr, 0, 6144);
}

// round 5
// speedup vs baseline: 3.2096x; 1.0882x over previous
#include <cuda_runtime.h>
#include <cuda_bf16.h>
#include <cstdint>

// ============================================================================
// AutoEncoder_BNN via mma.sync bf16 (portable to plain sm_103 ptxas target).
// fp32 GEMMs emulated as bf16 NT GEMM with K'=3K:
//   a = a_hi + a_lo :  A_cat = [A_hi | A_lo | A_hi],  B_cat = [B_hi | B_hi | B_lo]
//   => hi*hi + lo*hi + hi*lo  (dropped lo*lo ~2^-16 rel), fp32 accumulate.
// Engine: 128x128x64 tile, 8 warps (2x4), warp tile 64x32, m16n8k16 HMMA,
// 3-stage cp.async pipeline, SW128 swizzle, conflict-free ldmatrix.x4.
// R5: Karatsuba mixing — p,q only need Re=Gu-Bw, Im=Gw+Bu, obtained from
//   t1=u@G^T, t2=w@Bm^T, t3=(u+w)@(G+Bm)^T   (3 GEMMs instead of 4; -12% MACs)
// ============================================================================

// ---------------- device scratch (static; no runtime allocation) ------------
__device__ __nv_bfloat16 g_xcat [8192L  * 12288];  // x split      [8192,3*4096]
__device__ __nv_bfloat16 g_whcat[1024L  * 12288];  // W_h split
__device__ __nv_bfloat16 g_h1cat[8192L  * 3072];   // h1 split     [8192,3*1024]
__device__ __nv_bfloat16 g_wh2cat[1024L * 3072];
__device__ __nv_bfloat16 g_h2cat[8192L  * 3072];
__device__ __nv_bfloat16 g_wycat[4096L  * 3072];   // W_y split
__device__ __nv_bfloat16 g_uwcat[16384L * 6144];   // [u;w] split  [16384,3*2048]
__device__ __nv_bfloat16 g_sumcat[8192L * 6144];   // (u+w) split
__device__ __nv_bfloat16 g_gbmcat[4096L * 6144];   // [G;Bm] split (B-side)
__device__ __nv_bfloat16 g_gpbcat[2048L * 6144];   // (G+Bm) split (B-side)
__device__ float         g_t    [3L * 8192 * 2048]; // t1|t2|t3
__device__ __nv_bfloat16 g_ppcat[8192L  * 6144];
__device__ __nv_bfloat16 g_qpcat[8192L  * 6144];
__device__ __nv_bfloat16 g_wpcat[2048L  * 6144];
__device__ __nv_bfloat16 g_wqcat[2048L  * 6144];

// ---------------- PTX helpers ------------------------------------------------
__device__ __forceinline__ uint32_t smem_u32(const void* p) {
    uint32_t a;
    asm("{ .reg .u64 t; cvta.to.shared.u64 t, %1; cvt.u32.u64 %0, t; }" : "=r"(a) : "l"(p));
    return a;
}
__device__ __forceinline__ void cp_async16(uint32_t dst, const void* src) {
    asm volatile("cp.async.cg.shared.global [%0], [%1], 16;" :: "r"(dst), "l"(src) : "memory");
}
__device__ __forceinline__ void cp_commit() {
    asm volatile("cp.async.commit_group;" ::: "memory");
}
__device__ __forceinline__ void cp_wait1() {
    asm volatile("cp.async.wait_group 1;" ::: "memory");
}
__device__ __forceinline__ void ldsm4(uint32_t* r, uint32_t addr) {
    asm volatile("ldmatrix.sync.aligned.m8n8.x4.shared.b16 {%0,%1,%2,%3}, [%4];"
                 : "=r"(r[0]), "=r"(r[1]), "=r"(r[2]), "=r"(r[3]) : "r"(addr));
}
__device__ __forceinline__ void mma16816(float* c, const uint32_t* a, uint32_t b0, uint32_t b1) {
    asm volatile(
        "mma.sync.aligned.m16n8k16.row.col.f32.bf16.bf16.f32 "
        "{%0,%1,%2,%3}, {%4,%5,%6,%7}, {%8,%9}, {%0,%1,%2,%3};"
        : "+f"(c[0]), "+f"(c[1]), "+f"(c[2]), "+f"(c[3])
        : "r"(a[0]), "r"(a[1]), "r"(a[2]), "r"(a[3]), "r"(b0), "r"(b1));
}
__device__ __forceinline__ void split2(float a, float b, __nv_bfloat162& h, __nv_bfloat162& l) {
    __nv_bfloat16 ha = __float2bfloat16(a);
    __nv_bfloat16 hb = __float2bfloat16(b);
    h.x = ha; h.y = hb;
    l.x = __float2bfloat16(a - __bfloat162float(ha));
    l.y = __float2bfloat16(b - __bfloat162float(hb));
}

// ---------------- mma.sync GEMM ----------------------------------------------
// C[M,N] = act(A[M,K'] @ B[N,K']^T + bias); A,B bf16 K-major, fp32 accum.
// MODE 0: write fp32 C.
// MODE 1: write bf16 split (hi|lo|hi) to S with row stride 3*Nfull.
// MODE 2: write fp32 C (uw) AND split into stacked u/w buffer S [16384,6144].
constexpr int SMEM_BYTES = 3 * 32768;   // 3 stages x (A 16KB + B 16KB)

template <int MODE, bool RELU, bool BIAS>
__global__ __launch_bounds__(256, 2)
void gemm_mma(const __nv_bfloat16* __restrict__ A, int lda,
              const __nv_bfloat16* __restrict__ B, int ldb,
              const float* __restrict__ bias,
              float* __restrict__ C, int ldc,
              __nv_bfloat16* __restrict__ S, int Nfull, int K)
{
    extern __shared__ __align__(1024) char smem[];
    const uint32_t sb = smem_u32(smem);
    const int tid = threadIdx.x, lane = tid & 31, wid = tid >> 5;
    const int wm = wid & 1, wn = wid >> 1;            // warp grid 2(m) x 4(n)
    const int m0 = blockIdx.y * 128, n0 = blockIdx.x * 128;

    // ---- global->shared loader mapping (16B chunks, SW128 swizzle) ----
    const int lrow = tid >> 3;        // 0..31 (4 waves of 32 rows)
    const int lc16 = tid & 7;         // 16B chunk within 128B row
    uint32_t ld_off[4];
#pragma unroll
    for (int w2 = 0; w2 < 4; ++w2) {
        const int r = lrow + w2 * 32;
        ld_off[w2] = r * 128 + ((lc16 * 16) ^ ((r & 7) << 4));
    }
    const __nv_bfloat16* Ag = A + (size_t)(m0 + lrow) * lda + lc16 * 8;
    const __nv_bfloat16* Bg = B + (size_t)(n0 + lrow) * ldb + lc16 * 8;

    // ---- ldmatrix address precompute ----
    uint32_t aTerm[4], aXor[4];
#pragma unroll
    for (int mt = 0; mt < 4; ++mt) {
        const int r = wm * 64 + mt * 16 + ((lane >> 3) & 1) * 8 + (lane & 7);
        aTerm[mt] = r * 128; aXor[mt] = (r & 7) << 4;
    }
    const uint32_t aCol = (lane >> 4) * 16;
    uint32_t bTerm[2], bXor[2];
#pragma unroll
    for (int nt = 0; nt < 2; ++nt) {
        const int r = wn * 32 + nt * 16 + (lane >> 4) * 8 + (lane & 7);
        bTerm[nt] = r * 128; bXor[nt] = (r & 7) << 4;
    }
    const uint32_t bCol = ((lane >> 3) & 1) * 16;

    float acc[4][4][4];
#pragma unroll
    for (int mt = 0; mt < 4; ++mt)
#pragma unroll
        for (int n8 = 0; n8 < 4; ++n8)
#pragma unroll
            for (int j = 0; j < 4; ++j) acc[mt][n8][j] = 0.0f;

    const int nst = K / 64;

    auto issue = [&](int s, int kt) {
        const uint32_t sa = sb + (uint32_t)s * 32768u;
#pragma unroll
        for (int w2 = 0; w2 < 4; ++w2)
            cp_async16(sa + ld_off[w2], Ag + (size_t)w2 * 32 * lda + kt);
#pragma unroll
        for (int w2 = 0; w2 < 4; ++w2)
            cp_async16(sa + 16384u + ld_off[w2], Bg + (size_t)w2 * 32 * ldb + kt);
        cp_commit();
    };

    issue(0, 0);
    issue(1, 64);

    for (int i = 0; i < nst; ++i) {
        cp_wait1();
        __syncthreads();
        if (i + 2 < nst) issue((i + 2) % 3, (i + 2) * 64);
        else             cp_commit();            // keep group counting uniform

        const uint32_t sa = sb + (uint32_t)(i % 3) * 32768u;
        const uint32_t sB = sa + 16384u;
#pragma unroll
        for (int kk = 0; kk < 4; ++kk) {
            uint32_t a[4][4], b[2][4];
#pragma unroll
            for (int mt = 0; mt < 4; ++mt)
                ldsm4(a[mt], sa + aTerm[mt] + ((kk * 32 + aCol) ^ aXor[mt]));
#pragma unroll
            for (int nt = 0; nt < 2; ++nt)
                ldsm4(b[nt], sB + bTerm[nt] + ((kk * 32 + bCol) ^ bXor[nt]));
#pragma unroll
            for (int mt = 0; mt < 4; ++mt)
#pragma unroll
                for (int n8 = 0; n8 < 4; ++n8)
                    mma16816(acc[mt][n8], a[mt],
                             b[n8 >> 1][(n8 & 1) * 2], b[n8 >> 1][(n8 & 1) * 2 + 1]);
        }
        __syncthreads();
    }

    // ---- epilogue ----
    float bb[4][2];
#pragma unroll
    for (int n8 = 0; n8 < 4; ++n8) {
        if (BIAS) {
            const int col = n0 + wn * 32 + n8 * 8 + (lane & 3) * 2;
            bb[n8][0] = __ldg(&bias[col]);
            bb[n8][1] = __ldg(&bias[col + 1]);
        } else { bb[n8][0] = 0.0f; bb[n8][1] = 0.0f; }
    }

#pragma unroll
    for (int mt = 0; mt < 4; ++mt) {
#pragma unroll
        for (int half = 0; half < 2; ++half) {
            const int r = m0 + wm * 64 + mt * 16 + (lane >> 2) + half * 8;
#pragma unroll
            for (int n8 = 0; n8 < 4; ++n8) {
                const int col = n0 + wn * 32 + n8 * 8 + (lane & 3) * 2;
                float v0 = acc[mt][n8][half * 2 + 0] + bb[n8][0];
                float v1 = acc[mt][n8][half * 2 + 1] + bb[n8][1];
                if (RELU) { v0 = fmaxf(v0, 0.0f); v1 = fmaxf(v1, 0.0f); }
                if (MODE == 0 || MODE == 2)
                    *reinterpret_cast<float2*>(C + (size_t)r * ldc + col) = make_float2(v0, v1);
                if (MODE == 1) {
                    __nv_bfloat162 h, l; split2(v0, v1, h, l);
                    __nv_bfloat16* Sr = S + (size_t)r * (3 * Nfull) + col;
                    *reinterpret_cast<__nv_bfloat162*>(Sr)             = h;
                    *reinterpret_cast<__nv_bfloat162*>(Sr + Nfull)     = l;
                    *reinterpret_cast<__nv_bfloat162*>(Sr + 2 * Nfull) = h;
                }
                if (MODE == 2) {   // stacked: u rows [0,8192) | w rows [8192,16384)
                    const bool inU = (col < 2048);
                    const int rr = inU ? r : r + 8192;
                    const int cc = inU ? col : col - 2048;
                    __nv_bfloat162 h, l; split2(v0, v1, h, l);
                    __nv_bfloat16* Sr = S + (size_t)rr * 6144 + cc;
                    *reinterpret_cast<__nv_bfloat162*>(Sr)        = h;
                    *reinterpret_cast<__nv_bfloat162*>(Sr + 2048) = l;
                    *reinterpret_cast<__nv_bfloat162*>(Sr + 4096) = h;
                }
            }
        }
    }
}

// ------- pack: fp32 [R,C] -> bf16 split [R, 3C] -----------------------------
// B_SIDE=false (A operand): [hi | lo | hi].  B_SIDE=true (weights): [hi | hi | lo].
template <bool B_SIDE>
__global__ __launch_bounds__(256)
void pack2(const float* __restrict__ src, __nv_bfloat16* __restrict__ dst,
           int logC, long total)
{
    const long i = ((long)blockIdx.x * 256 + threadIdx.x) * 2;
    if (i >= total) return;
    const int  C = 1 << logC;
    const long r = i >> logC;
    const int  c = (int)(i & (C - 1));
    const float2 v = *reinterpret_cast<const float2*>(src + i);
    __nv_bfloat162 h, l; split2(v.x, v.y, h, l);
    __nv_bfloat16* d = dst + r * (3L * C) + c;
    if (B_SIDE) {
        *reinterpret_cast<__nv_bfloat162*>(d)         = h;
        *reinterpret_cast<__nv_bfloat162*>(d + C)     = h;
        *reinterpret_cast<__nv_bfloat162*>(d + 2 * C) = l;
    } else {
        *reinterpret_cast<__nv_bfloat162*>(d)         = h;
        *reinterpret_cast<__nv_bfloat162*>(d + C)     = l;
        *reinterpret_cast<__nv_bfloat162*>(d + 2 * C) = h;
    }
}

// ------- packadd2: (src0 + src1) -> B-side split [hi | hi | lo] --------------
__global__ __launch_bounds__(256)
void packadd2(const float* __restrict__ s0, const float* __restrict__ s1,
              __nv_bfloat16* __restrict__ dst, int logC, long total)
{
    const long i = ((long)blockIdx.x * 256 + threadIdx.x) * 2;
    if (i >= total) return;
    const int  C = 1 << logC;
    const long r = i >> logC;
    const int  c = (int)(i & (C - 1));
    const float2 a = *reinterpret_cast<const float2*>(s0 + i);
    const float2 b = *reinterpret_cast<const float2*>(s1 + i);
    __nv_bfloat162 h, l; split2(a.x + b.x, a.y + b.y, h, l);
    __nv_bfloat16* d = dst + r * (3L * C) + c;
    *reinterpret_cast<__nv_bfloat162*>(d)         = h;
    *reinterpret_cast<__nv_bfloat162*>(d + C)     = h;
    *reinterpret_cast<__nv_bfloat162*>(d + 2 * C) = l;
}

// ------- sumsplit: (u+w) from uw -> A-side split [8192, 3*2048] --------------
__global__ __launch_bounds__(256)
void sumsplit(const float* __restrict__ uw, __nv_bfloat16* __restrict__ dst)
{
    const long i = ((long)blockIdx.x * 256 + threadIdx.x) * 2;   // [0, 8192*2048)
    const long r = i >> 11;
    const int  c = (int)(i & 2047);
    const float2 u2 = *reinterpret_cast<const float2*>(uw + r * 4096 + c);
    const float2 w2 = *reinterpret_cast<const float2*>(uw + r * 4096 + 2048 + c);
    __nv_bfloat162 h, l; split2(u2.x + w2.x, u2.y + w2.y, h, l);
    __nv_bfloat16* d = dst + r * 6144 + c;
    *reinterpret_cast<__nv_bfloat162*>(d)        = h;
    *reinterpret_cast<__nv_bfloat162*>(d + 2048) = l;
    *reinterpret_cast<__nv_bfloat162*>(d + 4096) = h;
}

// ---------------- polar combine (Karatsuba) -> split pp/qp -------------------
// Re = t1 - t2, Im = t3 - t1 - t2;  p = u*Re + w*Im + bias_p;  q = w*Re - u*Im + bias_q
__global__ __launch_bounds__(256)
void combine(const float* __restrict__ uw, const float* __restrict__ t,
             const float* __restrict__ bias_p, const float* __restrict__ bias_q,
             __nv_bfloat16* __restrict__ ppcat, __nv_bfloat16* __restrict__ qpcat)
{
    const long i = ((long)blockIdx.x * 256 + threadIdx.x) * 2;   // [0, 8192*2048)
    const long r = i >> 11;
    const int  c = (int)(i & 2047);
    const float2 u2 = *reinterpret_cast<const float2*>(uw + r * 4096 + c);
    const float2 w2 = *reinterpret_cast<const float2*>(uw + r * 4096 + 2048 + c);
    const float2 t1 = *reinterpret_cast<const float2*>(t + i);
    const float2 t2 = *reinterpret_cast<const float2*>(t + 8192L * 2048 + i);
    const float2 t3 = *reinterpret_cast<const float2*>(t + 2L * 8192 * 2048 + i);
    const float2 bp = *reinterpret_cast<const float2*>(bias_p + c);
    const float2 bq = *reinterpret_cast<const float2*>(bias_q + c);
    const float re0 = t1.x - t2.x, re1 = t1.y - t2.y;
    const float im0 = t3.x - t1.x - t2.x, im1 = t3.y - t1.y - t2.y;
    const float p0 = u2.x * re0 + w2.x * im0 + bp.x;
    const float p1 = u2.y * re1 + w2.y * im1 + bp.y;
    const float q0 = w2.x * re0 - u2.x * im0 + bq.x;
    const float q1 = w2.y * re1 - u2.y * im1 + bq.y;
    __nv_bfloat162 h, l;
    __nv_bfloat16* d = ppcat + r * 6144 + c;
    split2(p0, p1, h, l);
    *reinterpret_cast<__nv_bfloat162*>(d)        = h;
    *reinterpret_cast<__nv_bfloat162*>(d + 2048) = l;
    *reinterpret_cast<__nv_bfloat162*>(d + 4096) = h;
    d = qpcat + r * 6144 + c;
    split2(q0, q1, h, l);
    *reinterpret_cast<__nv_bfloat162*>(d)        = h;
    *reinterpret_cast<__nv_bfloat162*>(d + 2048) = l;
    *reinterpret_cast<__nv_bfloat162*>(d + 4096) = h;
}

// ---------------- host side --------------------------------------------------
extern "C" void kernel_launch(void* const* d_in, const int* in_sizes, int n_in,
                              void* d_out, int out_size)
{
    const float* x      = (const float*)d_in[0];
    const float* W_h    = (const float*)d_in[1];
    const float* b_h    = (const float*)d_in[2];
    const float* W_h2   = (const float*)d_in[3];
    const float* b_h2   = (const float*)d_in[4];
    const float* W_y    = (const float*)d_in[5];
    const float* b_y    = (const float*)d_in[6];
    const float* G      = (const float*)d_in[7];
    const float* Bm     = (const float*)d_in[8];
    const float* bias_p = (const float*)d_in[9];
    const float* bias_q = (const float*)d_in[10];
    const float* W_p    = (const float*)d_in[11];
    const float* b_p    = (const float*)d_in[12];
    const float* W_q    = (const float*)d_in[13];
    const float* b_q    = (const float*)d_in[14];

    float* out = (float*)d_out;
    float* uw  = out;                                 // [8192,4096]
    float* p   = out + (size_t)8192 * 4096;           // [8192,2048]
    float* q   = p   + (size_t)8192 * 2048;           // [8192,2048]

    __nv_bfloat16 *xcat, *whcat, *h1cat, *wh2cat, *h2cat, *wycat, *uwcat,
                  *sumcat, *gbmcat, *gpbcat, *ppcat, *qpcat, *wpcat, *wqcat;
    float* t;
    cudaGetSymbolAddress((void**)&xcat,  g_xcat);
    cudaGetSymbolAddress((void**)&whcat, g_whcat);
    cudaGetSymbolAddress((void**)&h1cat, g_h1cat);
    cudaGetSymbolAddress((void**)&wh2cat,g_wh2cat);
    cudaGetSymbolAddress((void**)&h2cat, g_h2cat);
    cudaGetSymbolAddress((void**)&wycat, g_wycat);
    cudaGetSymbolAddress((void**)&uwcat, g_uwcat);
    cudaGetSymbolAddress((void**)&sumcat,g_sumcat);
    cudaGetSymbolAddress((void**)&gbmcat,g_gbmcat);
    cudaGetSymbolAddress((void**)&gpbcat,g_gpbcat);
    cudaGetSymbolAddress((void**)&t,     g_t);
    cudaGetSymbolAddress((void**)&ppcat, g_ppcat);
    cudaGetSymbolAddress((void**)&qpcat, g_qpcat);
    cudaGetSymbolAddress((void**)&wpcat, g_wpcat);
    cudaGetSymbolAddress((void**)&wqcat, g_wqcat);

    cudaFuncSetAttribute(gemm_mma<1, true,  true >, cudaFuncAttributeMaxDynamicSharedMemorySize, SMEM_BYTES);
    cudaFuncSetAttribute(gemm_mma<2, false, true >, cudaFuncAttributeMaxDynamicSharedMemorySize, SMEM_BYTES);
    cudaFuncSetAttribute(gemm_mma<0, false, false>, cudaFuncAttributeMaxDynamicSharedMemorySize, SMEM_BYTES);
    cudaFuncSetAttribute(gemm_mma<0, false, true >, cudaFuncAttributeMaxDynamicSharedMemorySize, SMEM_BYTES);

    // ---- packs: x is A-side [hi|lo|hi]; all weights are B-side [hi|hi|lo] ----
    pack2<false><<<(8192L * 4096 / 2 + 255) / 256, 256>>>(x,    xcat,   12, 8192L * 4096);
    pack2<true ><<<(1024L * 4096 / 2 + 255) / 256, 256>>>(W_h,  whcat,  12, 1024L * 4096);
    pack2<true ><<<(1024L * 1024 / 2 + 255) / 256, 256>>>(W_h2, wh2cat, 10, 1024L * 1024);
    pack2<true ><<<(4096L * 1024 / 2 + 255) / 256, 256>>>(W_y,  wycat,  10, 4096L * 1024);
    pack2<true ><<<(2048L * 2048 / 2 + 255) / 256, 256>>>(G,    gbmcat,                11, 2048L * 2048);
    pack2<true ><<<(2048L * 2048 / 2 + 255) / 256, 256>>>(Bm,   gbmcat + 2048L * 6144, 11, 2048L * 2048);
    packadd2   <<<(2048L * 2048 / 2 + 255) / 256, 256>>>(G, Bm, gpbcat, 11, 2048L * 2048);
    pack2<true ><<<(2048L * 2048 / 2 + 255) / 256, 256>>>(W_p,  wpcat,  11, 2048L * 2048);
    pack2<true ><<<(2048L * 2048 / 2 + 255) / 256, 256>>>(W_q,  wqcat,  11, 2048L * 2048);

    const dim3 blk(256);
    // G1: h1 = relu(x @ W_h^T + b_h)          -> split h1cat
    gemm_mma<1, true,  true ><<<dim3(1024 / 128, 8192 / 128), blk, SMEM_BYTES>>>(
        xcat, 12288, whcat, 12288, b_h, nullptr, 0, h1cat, 1024, 12288);
    // G2: h2 = relu(h1 @ W_h2^T + b_h2)       -> split h2cat
    gemm_mma<1, true,  true ><<<dim3(1024 / 128, 8192 / 128), blk, SMEM_BYTES>>>(
        h1cat, 3072, wh2cat, 3072, b_h2, nullptr, 0, h2cat, 1024, 3072);
    // G3: uw = h2 @ W_y^T + b_y               -> f32 uw (d_out) + stacked split uwcat
    gemm_mma<2, false, true ><<<dim3(4096 / 128, 8192 / 128), blk, SMEM_BYTES>>>(
        h2cat, 3072, wycat, 3072, b_y, uw, 4096, uwcat, 4096, 3072);
    // (u+w) split for Karatsuba
    sumsplit<<<(8192L * 2048 / 2) / 256, 256>>>(uw, sumcat);
    // Karatsuba mixing: t1 = u@G^T, t2 = w@Bm^T, t3 = (u+w)@(G+Bm)^T
    gemm_mma<0, false, false><<<dim3(2048 / 128, 8192 / 128), blk, SMEM_BYTES>>>(
        uwcat,                6144, gbmcat,                6144, nullptr,
        t,                    2048, nullptr, 0, 6144);
    gemm_mma<0, false, false><<<dim3(2048 / 128, 8192 / 128), blk, SMEM_BYTES>>>(
        uwcat + 8192L * 6144, 6144, gbmcat + 2048L * 6144, 6144, nullptr,
        t + 8192L * 2048,     2048, nullptr, 0, 6144);
    gemm_mma<0, false, false><<<dim3(2048 / 128, 8192 / 128), blk, SMEM_BYTES>>>(
        sumcat,               6144, gpbcat,                6144, nullptr,
        t + 2L * 8192 * 2048, 2048, nullptr, 0, 6144);
    // combine -> split pp/qp
    combine<<<(8192L * 2048 / 2) / 256, 256>>>(uw, t, bias_p, bias_q, ppcat, qpcat);
    // G5/G6: final projections
    gemm_mma<0, false, true ><<<dim3(2048 / 128, 8192 / 128), blk, SMEM_BYTES>>>(
        ppcat, 6144, wpcat, 6144, b_p, p, 2048, nullptr, 0, 6144);
    gemm_mma<0, false, true ><<<dim3(2048 / 128, 8192 / 128), blk, SMEM_BYTES>>>(
        qpcat, 6144, wqcat, 6144, b_q, q, 2048, nullptr, 0, 6144);
}